// round 15
// baseline (speedup 1.0000x reference)
#include <cuda_runtime.h>
#include <cuda_bf16.h>
#include <cuda_fp16.h>
#include <math.h>
#include <stdint.h>

// Problem constants (fixed by setup_inputs)
#define DD    768
#define TAGS  5
#define LQ    128
#define BQC   200      // B*N*Q*N
#define BNQ   40       // B*N*Q
#define BNKC  50       // B*N*K
#define NPROT 10       // B*N
#define FD    3072     // 4*D
#define MBIG  25600    // BQC*LQ

// ---------------- scratch (device globals) --------------
__device__ float g_protok[BNKC*TAGS*DD];
__device__ float g_proto [NPROT*TAGS*DD];
__device__ float g_pw2   [NPROT*TAGS*DD];
__device__ float g_att   [BQC*TAGS*LQ];
__device__ float g_P     [BQC*LQ*TAGS];
__device__ __half g_A16h[(size_t)MBIG*1536];     // fp16 big-GEMM A
__device__ __half g_W16f[(size_t)DD*FD];         // fp16 proj_w (full)
__device__ __half g_RW16[(size_t)DD*FD];         // fp16 rel_w1
__device__ __half g_Q16 [(size_t)BNQ*LQ*DD];     // fp16 q_emb
__device__ __half g_FS16[(size_t)1024*FD];       // fp16 fuse-support rows (hi)
__device__ __half g_FS16l[(size_t)1024*FD];      // fp16 lo residual
__device__ __half g_C16 [(size_t)256*FD];        // fp16 cat rows (hi)
__device__ __half g_C16l[(size_t)256*FD];        // fp16 lo residual
__device__ float g_T1    [BNQ*LQ*DD];
__device__ float g_es    [BQC*TAGS*DD];
__device__ float g_eqmax [BQC*DD];
__device__ float g_eqsum [BQC*DD];

__device__ __forceinline__ float warpMax(float v){
    #pragma unroll
    for (int o=16;o;o>>=1) v = fmaxf(v, __shfl_xor_sync(0xffffffffu, v, o));
    return v;
}
__device__ __forceinline__ float warpSum(float v){
    #pragma unroll
    for (int o=16;o;o>>=1) v += __shfl_xor_sync(0xffffffffu, v, o);
    return v;
}

// ================= HMMA helpers =================
__device__ __forceinline__ uint32_t smem_u32(const void* p) {
    uint32_t a;
    asm("{ .reg .u64 t; cvta.to.shared.u64 t, %1; cvt.u32.u64 %0, t; }" : "=r"(a) : "l"(p));
    return a;
}
__device__ __forceinline__ void cp16(uint32_t dst, const void* src){
    asm volatile("cp.async.cg.shared.global [%0], [%1], 16;" :: "r"(dst), "l"(src) : "memory");
}
__device__ __forceinline__ void cp_commit(){ asm volatile("cp.async.commit_group;" ::: "memory"); }
template<int N> __device__ __forceinline__ void cp_waitg(){
    asm volatile("cp.async.wait_group %0;" :: "n"(N) : "memory");
}
__device__ __forceinline__ void ldsm4(uint32_t a, uint32_t* r){
    asm volatile("ldmatrix.sync.aligned.m8n8.x4.shared.b16 {%0,%1,%2,%3}, [%4];"
        : "=r"(r[0]),"=r"(r[1]),"=r"(r[2]),"=r"(r[3]) : "r"(a));
}
__device__ __forceinline__ void mma16816h(float* c, const uint32_t* a, const uint32_t* b){
    asm volatile("mma.sync.aligned.m16n8k16.row.col.f32.f16.f16.f32 "
        "{%0,%1,%2,%3},{%4,%5,%6,%7},{%8,%9},{%0,%1,%2,%3};"
        : "+f"(c[0]),"+f"(c[1]),"+f"(c[2]),"+f"(c[3])
        : "r"(a[0]),"r"(a[1]),"r"(a[2]),"r"(a[3]), "r"(b[0]),"r"(b[1]));
}
__device__ __forceinline__ uint32_t tile_off(int m, int k8){
    return (uint32_t)((m*4 + (k8 ^ ((m>>1)&3))) << 4);
}
__device__ __forceinline__ uint32_t pack2h(float a, float b){
    return (uint32_t)__half_as_ushort(__float2half(a))
         | ((uint32_t)__half_as_ushort(__float2half(b)) << 16);
}

#define TBUF  8192
#define HSTG  (2*TBUF)       // fp16 1-product stage: A | B
#define HSTG2 (3*TBUF)       // fp16 2-product stage: Ah | Al | B
#define DSMEM2 (3*HSTG2)     // 72 KB

// ================= fp16 single-product HMMA GEMM =================
template<int KDIM, int MDIM, bool RELU>
__device__ void dev_hgemm16(int bx, int by,
                            const __half* __restrict__ A_,
                            const __half* __restrict__ B_, int bsb,
                            float* __restrict__ C,
                            const float* __restrict__ bias,
                            char* ds)
{
    constexpr int NC = KDIM / 32;
    int tid = threadIdx.x;
    int lane = tid & 31, wid = tid >> 5;
    int wm = wid & 1, wn = wid >> 1;
    int m0 = by * 128, n0 = bx * 128;
    uint32_t sbase = smem_u32(ds);

    const char* gA = (const char*)A_ + (size_t)m0*KDIM*2;
    const char* gB = (const char*)B_ + (size_t)n0*bsb;

    float acc[4][4][4];
    #pragma unroll
    for (int a=0;a<4;a++)
        #pragma unroll
        for (int b=0;b<4;b++)
            #pragma unroll
            for (int r=0;r<4;r++) acc[a][b][r] = 0.f;

    int r0 = tid >> 2, k80 = tid & 3;
    int r1 = r0 + 64;
    uint32_t d0 = tile_off(r0, k80);
    uint32_t d1 = tile_off(r1, k80);

    auto issue = [&](int c){
        size_t koff = (size_t)c*64 + (size_t)k80*16;
        uint32_t sb = sbase + (c % 3)*HSTG;
        size_t sa0 = (size_t)r0*(KDIM*2) + koff;
        size_t sa1 = (size_t)r1*(KDIM*2) + koff;
        size_t sb0 = (size_t)r0*bsb + koff;
        size_t sb1 = (size_t)r1*bsb + koff;
        cp16(sb + d0,        gA + sa0);  cp16(sb + d1,        gA + sa1);
        cp16(sb + TBUF + d0, gB + sb0);  cp16(sb + TBUF + d1, gB + sb1);
        cp_commit();
    };

    issue(0);
    issue(1);

    int a_m  = (lane & 15);
    int a_k8 = (lane >> 4);
    int b_n  = (lane & 7) + ((lane >> 4) << 3);
    int b_k8 = (lane >> 3) & 1;

    for (int c = 0; c < NC; c++){
        if (c + 1 < NC) cp_waitg<1>(); else cp_waitg<0>();
        __syncthreads();
        uint32_t ah = sbase + (c % 3)*HSTG;
        uint32_t bh = ah + TBUF;
        #pragma unroll
        for (int ks = 0; ks < 2; ks++){
            int ks8 = ks*2;
            uint32_t Bhf[2][4], Af[4][4];
            #pragma unroll
            for (int p=0; p<2; p++){
                int n = wn*32 + p*16 + b_n;
                ldsm4(bh + tile_off(n, ks8 + b_k8), Bhf[p]);
            }
            #pragma unroll
            for (int mt=0; mt<4; mt++){
                int m = wm*64 + mt*16 + a_m;
                ldsm4(ah + tile_off(m, ks8 + a_k8), Af[mt]);
            }
            #pragma unroll
            for (int mt=0; mt<4; mt++)
                #pragma unroll
                for (int nt=0; nt<4; nt++)
                    mma16816h(acc[mt][nt], Af[mt], &Bhf[nt>>1][(nt&1)*2]);
        }
        if (c + 2 < NC) issue(c+2);
    }

    int row = lane >> 2, colb = (lane & 3)*2;
    #pragma unroll
    for (int mt=0; mt<4; mt++){
        #pragma unroll
        for (int h2=0; h2<2; h2++){
            int gm = m0 + wm*64 + mt*16 + row + h2*8;
            if (gm < MDIM){
                #pragma unroll
                for (int nt=0; nt<4; nt++){
                    int cl = wn*32 + nt*8 + colb;
                    int gn = n0 + cl;
                    float v0 = acc[mt][nt][h2*2+0];
                    float v1 = acc[mt][nt][h2*2+1];
                    if (RELU){
                        v0 = fmaxf(v0 + bias[gn], 0.f);
                        v1 = fmaxf(v1 + bias[gn+1], 0.f);
                    }
                    C[(size_t)gm*DD + gn]   = v0;
                    C[(size_t)gm*DD + gn+1] = v1;
                }
            }
        }
    }
}

// ================= fp16 2-product HMMA GEMM (A = hi + lo) =================
// FUSE_LOGITS: instead of storing C, atomicAdd per-row partial dot with w2.
template<int KDIM, int MDIM, bool RELU, bool FUSE_LOGITS>
__device__ void dev_hgemm16_2p(int bx, int by,
                               const __half* __restrict__ Ah_,
                               const __half* __restrict__ Al_,
                               const __half* __restrict__ B_, int bsb,
                               float* __restrict__ C,
                               const float* __restrict__ bias,
                               const float* __restrict__ w2,
                               float* __restrict__ outp,
                               char* ds)
{
    constexpr int NC = KDIM / 32;
    int tid = threadIdx.x;
    int lane = tid & 31, wid = tid >> 5;
    int wm = wid & 1, wn = wid >> 1;
    int m0 = by * 128, n0 = bx * 128;
    uint32_t sbase = smem_u32(ds);

    const char* gAh = (const char*)Ah_ + (size_t)m0*KDIM*2;
    const char* gAl = (const char*)Al_ + (size_t)m0*KDIM*2;
    const char* gB  = (const char*)B_ + (size_t)n0*bsb;

    float acc[4][4][4];
    #pragma unroll
    for (int a=0;a<4;a++)
        #pragma unroll
        for (int b=0;b<4;b++)
            #pragma unroll
            for (int r=0;r<4;r++) acc[a][b][r] = 0.f;

    int r0 = tid >> 2, k80 = tid & 3;
    int r1 = r0 + 64;
    uint32_t d0 = tile_off(r0, k80);
    uint32_t d1 = tile_off(r1, k80);

    auto issue = [&](int c){
        size_t koff = (size_t)c*64 + (size_t)k80*16;
        uint32_t sb = sbase + (c % 3)*HSTG2;
        size_t sa0 = (size_t)r0*(KDIM*2) + koff;
        size_t sa1 = (size_t)r1*(KDIM*2) + koff;
        size_t sb0 = (size_t)r0*bsb + koff;
        size_t sb1 = (size_t)r1*bsb + koff;
        cp16(sb + d0,          gAh + sa0);  cp16(sb + d1,          gAh + sa1);
        cp16(sb + TBUF + d0,   gAl + sa0);  cp16(sb + TBUF + d1,   gAl + sa1);
        cp16(sb + 2*TBUF + d0, gB + sb0);   cp16(sb + 2*TBUF + d1, gB + sb1);
        cp_commit();
    };

    issue(0);
    issue(1);

    int a_m  = (lane & 15);
    int a_k8 = (lane >> 4);
    int b_n  = (lane & 7) + ((lane >> 4) << 3);
    int b_k8 = (lane >> 3) & 1;

    for (int c = 0; c < NC; c++){
        if (c + 1 < NC) cp_waitg<1>(); else cp_waitg<0>();
        __syncthreads();
        uint32_t ah = sbase + (c % 3)*HSTG2;
        uint32_t al = ah + TBUF;
        uint32_t bh = ah + 2*TBUF;
        #pragma unroll
        for (int ks = 0; ks < 2; ks++){
            int ks8 = ks*2;
            uint32_t Bhf[2][4], Af[4][4];
            #pragma unroll
            for (int p=0; p<2; p++){
                int n = wn*32 + p*16 + b_n;
                ldsm4(bh + tile_off(n, ks8 + b_k8), Bhf[p]);
            }
            #pragma unroll
            for (int mt=0; mt<4; mt++){
                int m = wm*64 + mt*16 + a_m;
                ldsm4(ah + tile_off(m, ks8 + a_k8), Af[mt]);
            }
            #pragma unroll
            for (int mt=0; mt<4; mt++)
                #pragma unroll
                for (int nt=0; nt<4; nt++)
                    mma16816h(acc[mt][nt], Af[mt], &Bhf[nt>>1][(nt&1)*2]);
            #pragma unroll
            for (int mt=0; mt<4; mt++){
                int m = wm*64 + mt*16 + a_m;
                ldsm4(al + tile_off(m, ks8 + a_k8), Af[mt]);
            }
            #pragma unroll
            for (int mt=0; mt<4; mt++)
                #pragma unroll
                for (int nt=0; nt<4; nt++)
                    mma16816h(acc[mt][nt], Af[mt], &Bhf[nt>>1][(nt&1)*2]);
        }
        if (c + 2 < NC) issue(c+2);
    }

    int row = lane >> 2, colb = (lane & 3)*2;
    #pragma unroll
    for (int mt=0; mt<4; mt++){
        #pragma unroll
        for (int h2=0; h2<2; h2++){
            int gm = m0 + wm*64 + mt*16 + row + h2*8;
            if (gm < MDIM){
                float part = 0.f;
                #pragma unroll
                for (int nt=0; nt<4; nt++){
                    int cl = wn*32 + nt*8 + colb;
                    int gn = n0 + cl;
                    float v0 = acc[mt][nt][h2*2+0];
                    float v1 = acc[mt][nt][h2*2+1];
                    if (RELU){
                        v0 = fmaxf(v0 + bias[gn], 0.f);
                        v1 = fmaxf(v1 + bias[gn+1], 0.f);
                    }
                    if (FUSE_LOGITS){
                        part += v0*w2[gn] + v1*w2[gn+1];
                    } else {
                        C[(size_t)gm*DD + gn]   = v0;
                        C[(size_t)gm*DD + gn+1] = v1;
                    }
                }
                if (FUSE_LOGITS) atomicAdd(&outp[gm], part);
            }
        }
    }
}

// ================= big GEMM device core (fp16 1-product, fused epilogue) ========
#define NCCH  48
__device__ void dev_big(int bx, int by,
                        const float* __restrict__ q_mask,
                        const float* __restrict__ proj_b,
                        char* ds)
{
    __shared__ float s_pwr[5*128];
    __shared__ float s_P[640];
    __shared__ float s_qm[128];
    __shared__ float s_bias[128];
    __shared__ float s_rmax[2][128];
    __shared__ float s_rsum[2][128];

    int tid = threadIdx.x;
    int lane = tid & 31, wid = tid >> 5;
    int wm = wid & 1;
    int wn = wid >> 1;
    int bq  = by;
    int n0  = bx * 128;
    int qi  = bq / 5;
    int pi  = (bq / 100)*5 + (bq % 5);

    uint32_t sbase = smem_u32(ds);

    for (int i = tid; i < 5*128; i += 256){
        int s = i >> 7, c = i & 127;
        s_pwr[i] = g_pw2[((size_t)pi*5 + s)*DD + n0 + c];
    }
    for (int i = tid; i < 640; i += 256) s_P[i] = g_P[(size_t)bq*640 + i];
    if (tid < 128){ s_qm[tid] = q_mask[qi*128 + tid]; s_bias[tid] = proj_b[n0 + tid]; }

    const char* gAh = (const char*)g_A16h + (size_t)bq*128*3072;
    const char* gBh = (const char*)g_W16f + (size_t)n0*6144 + 3072;

    float acc[4][4][4];
    #pragma unroll
    for (int a=0;a<4;a++)
        #pragma unroll
        for (int b=0;b<4;b++)
            #pragma unroll
            for (int r=0;r<4;r++) acc[a][b][r] = 0.f;

    int r0 = tid >> 2, k80 = tid & 3;
    int r1 = r0 + 64;
    uint32_t d0 = tile_off(r0, k80);
    uint32_t d1 = tile_off(r1, k80);

    auto issue = [&](int c){
        size_t koff = (size_t)c*64 + (size_t)k80*16;
        uint32_t sb = sbase + (c % 3)*HSTG;
        size_t sa0 = (size_t)r0*3072 + koff;
        size_t sa1 = (size_t)r1*3072 + koff;
        size_t sb0 = (size_t)r0*6144 + koff;
        size_t sb1 = (size_t)r1*6144 + koff;
        cp16(sb + d0,        gAh + sa0);  cp16(sb + d1,        gAh + sa1);
        cp16(sb + TBUF + d0, gBh + sb0);  cp16(sb + TBUF + d1, gBh + sb1);
        cp_commit();
    };

    issue(0);
    issue(1);

    int a_m  = (lane & 15);
    int a_k8 = (lane >> 4);
    int b_n  = (lane & 7) + ((lane >> 4) << 3);
    int b_k8 = (lane >> 3) & 1;

    for (int c = 0; c < NCCH; c++){
        if (c + 1 < NCCH) cp_waitg<1>(); else cp_waitg<0>();
        __syncthreads();
        uint32_t ah = sbase + (c % 3)*HSTG;
        uint32_t bh = ah + TBUF;
        #pragma unroll
        for (int ks = 0; ks < 2; ks++){
            int ks8 = ks*2;
            uint32_t Bhf[2][4], Af[4][4];
            #pragma unroll
            for (int p=0; p<2; p++){
                int n = wn*32 + p*16 + b_n;
                ldsm4(bh + tile_off(n, ks8 + b_k8), Bhf[p]);
            }
            #pragma unroll
            for (int mt=0; mt<4; mt++){
                int m = wm*64 + mt*16 + a_m;
                ldsm4(ah + tile_off(m, ks8 + a_k8), Af[mt]);
            }
            #pragma unroll
            for (int mt=0; mt<4; mt++)
                #pragma unroll
                for (int nt=0; nt<4; nt++)
                    mma16816h(acc[mt][nt], Af[mt], &Bhf[nt>>1][(nt&1)*2]);
        }
        if (c + 2 < NCCH) issue(c+2);
    }

    // fused epilogue
    int row = lane >> 2, colb = (lane & 3)*2;
    float lmax[4][2], lsum[4][2];
    #pragma unroll
    for (int nt=0; nt<4; nt++)
        #pragma unroll
        for (int j=0;j<2;j++){ lmax[nt][j] = 0.f; lsum[nt][j] = 0.f; }

    #pragma unroll
    for (int mt=0; mt<4; mt++){
        #pragma unroll
        for (int h2=0; h2<2; h2++){
            int q = wm*64 + mt*16 + row + h2*8;
            float qm = s_qm[q];
            float p0=s_P[q*5+0], p1=s_P[q*5+1], p2=s_P[q*5+2], p3=s_P[q*5+3], p4=s_P[q*5+4];
            const float* t1row = g_T1 + ((size_t)qi*128 + q)*DD + n0;
            #pragma unroll
            for (int nt=0; nt<4; nt++){
                int cl = wn*32 + nt*8 + colb;
                float2 t1 = *(const float2*)(t1row + cl);
                float t2a = qm*(p0*s_pwr[cl] + p1*s_pwr[128+cl] + p2*s_pwr[256+cl]
                              + p3*s_pwr[384+cl] + p4*s_pwr[512+cl]);
                float t2b = qm*(p0*s_pwr[cl+1] + p1*s_pwr[128+cl+1] + p2*s_pwr[256+cl+1]
                              + p3*s_pwr[384+cl+1] + p4*s_pwr[512+cl+1]);
                float v0 = fmaxf(acc[mt][nt][h2*2+0] + t1.x + t2a + s_bias[cl], 0.f);
                float v1 = fmaxf(acc[mt][nt][h2*2+1] + t1.y + t2b + s_bias[cl+1], 0.f);
                lmax[nt][0] = fmaxf(lmax[nt][0], v0); lsum[nt][0] += v0;
                lmax[nt][1] = fmaxf(lmax[nt][1], v1); lsum[nt][1] += v1;
            }
        }
    }
    #pragma unroll
    for (int o = 4; o <= 16; o <<= 1){
        #pragma unroll
        for (int nt=0; nt<4; nt++)
            #pragma unroll
            for (int j=0;j<2;j++){
                lmax[nt][j] = fmaxf(lmax[nt][j], __shfl_xor_sync(0xffffffffu, lmax[nt][j], o));
                lsum[nt][j] += __shfl_xor_sync(0xffffffffu, lsum[nt][j], o);
            }
    }
    if (row == 0){
        #pragma unroll
        for (int nt=0; nt<4; nt++){
            int cl = wn*32 + nt*8 + colb;
            s_rmax[wm][cl]   = lmax[nt][0];  s_rsum[wm][cl]   = lsum[nt][0];
            s_rmax[wm][cl+1] = lmax[nt][1];  s_rsum[wm][cl+1] = lsum[nt][1];
        }
    }
    __syncthreads();
    if (tid < 128){
        g_eqmax[(size_t)bq*DD + n0 + tid] = fmaxf(s_rmax[0][tid], s_rmax[1][tid]);
        g_eqsum[(size_t)bq*DD + n0 + tid] = s_rsum[0][tid] + s_rsum[1][tid];
    }
}

// ================= prep paths =================
__device__ void dev_proto(int bnk, const float* __restrict__ s_emb,
                          const float* __restrict__ s_mask,
                          const float* __restrict__ s_label)
{
    __shared__ int   tags[128];
    __shared__ float wts[128];
    __shared__ float cnt[TAGS];
    int tid = threadIdx.x;
    if (tid < 128) {
        const float* lr = s_label + ((size_t)bnk*128 + tid)*TAGS;
        float best = lr[0]; int bi = 0;
        #pragma unroll
        for (int s=1;s<TAGS;s++){ float v = lr[s]; if (v > best){ best = v; bi = s; } }
        tags[tid] = bi;
        wts[tid]  = (bi == 0) ? s_mask[bnk*128 + tid] : 1.0f;
    }
    __syncthreads();
    if (tid < TAGS) {
        float c = 0.f;
        for (int t=0;t<128;t++) if (tags[t] == tid) c += wts[t];
        cnt[tid] = c;
    }
    __syncthreads();
    float acc[TAGS][3];
    #pragma unroll
    for (int k=0;k<TAGS;k++)
        #pragma unroll
        for (int j=0;j<3;j++) acc[k][j] = 0.f;
    const float* eb = s_emb + (size_t)bnk*128*DD;
    for (int t=0;t<128;t++){
        int tg = tags[t]; float w = wts[t];
        #pragma unroll
        for (int j=0;j<3;j++){
            float e = eb[t*DD + tid + j*256];
            #pragma unroll
            for (int k=0;k<TAGS;k++)
                acc[k][j] += ((tg == k) ? w : 0.0f) * e;
        }
    }
    #pragma unroll
    for (int k=0;k<TAGS;k++){
        float c = cnt[k];
        float inv = (c > 0.f) ? (1.0f / fmaxf(c, 1.0f)) : 0.0f;
        #pragma unroll
        for (int j=0;j<3;j++){
            int d = tid + j*256;
            g_protok[((size_t)bnk*TAGS + k)*DD + d] = (c > 0.f) ? acc[k][j]*inv : 0.0f;
        }
    }
}

__device__ __forceinline__ void cast8(const float* __restrict__ src,
                                      __half* __restrict__ dst, size_t i0)
{
    float4 a = *(const float4*)(src + i0);
    float4 b = *(const float4*)(src + i0 + 4);
    uint4 o;
    o.x = pack2h(a.x, a.y); o.y = pack2h(a.z, a.w);
    o.z = pack2h(b.x, b.y); o.w = pack2h(b.z, b.w);
    *(uint4*)(dst + i0) = o;
}

#define WBLK 1152   // DD*FD/2048
#define QBLK 1920   // BNQ*LQ*DD/2048

__global__ void __launch_bounds__(256) k_prep(const float* __restrict__ s_emb,
                                              const float* __restrict__ s_mask,
                                              const float* __restrict__ s_label,
                                              const float* __restrict__ proj_w,
                                              const float* __restrict__ rel_w1,
                                              const float* __restrict__ q_emb)
{
    int b = blockIdx.x;
    if (b < 50){ dev_proto(b, s_emb, s_mask, s_label); return; }
    int tid = threadIdx.x;
    if (b < 50 + WBLK){ cast8(proj_w, g_W16f, ((size_t)(b-50)*256 + tid)*8); return; }
    if (b < 50 + 2*WBLK){ cast8(rel_w1, g_RW16, ((size_t)(b-50-WBLK)*256 + tid)*8); return; }
    cast8(q_emb, g_Q16, ((size_t)(b-50-2*WBLK)*256 + tid)*8);
}

__global__ void proto_avg_kernel()
{
    int i = blockIdx.x*256 + threadIdx.x;
    int pi = i / (TAGS*DD), rem = i % (TAGS*DD);
    float s = 0.f;
    #pragma unroll
    for (int k=0;k<5;k++) s += g_protok[((size_t)(pi*5 + k))*(TAGS*DD) + rem];
    g_proto[i] = s * 0.2f;
}

// ================= att (4-way split, fused s-softmax) | pw2 | T1 hgemm16 =========
__global__ void __launch_bounds__(256,2) k_att_pw2_t1(const float* __restrict__ q_emb,
                                                      const float* __restrict__ q_mask,
                                                      const float* __restrict__ Bw)
{
    extern __shared__ __align__(128) char ds[];
    if (blockIdx.x < 4*BNQ){
        float* sp = (float*)ds;            // 25 x 768
        int qi = blockIdx.x >> 2, quarter = blockIdx.x & 3;
        int tid = threadIdx.x;
        int b = qi / 20;
        const float* pb = g_proto + (size_t)b*25*DD;
        for (int i = tid; i < 25*DD; i += 256) sp[i] = pb[i];
        __syncthreads();
        int wid = tid >> 5, lane = tid & 31;
        const float4* sp4 = (const float4*)sp;
        int rq0 = quarter*32;
        for (int r = rq0 + wid; r < rq0 + 32; r += 8){
            const float4* qr4 = (const float4*)(q_emb + ((size_t)qi*128 + r)*DD);
            float acc[25];
            #pragma unroll
            for (int t=0;t<25;t++) acc[t] = 0.f;
            for (int d4 = lane; d4 < 192; d4 += 32){
                float4 qv = qr4[d4];
                #pragma unroll
                for (int t=0;t<25;t++){
                    float4 sv = sp4[t*192 + d4];
                    acc[t] += qv.x*sv.x + qv.y*sv.y + qv.z*sv.z + qv.w*sv.w;
                }
            }
            float sums[25];
            #pragma unroll
            for (int t=0;t<25;t++) sums[t] = warpSum(acc[t]);
            float qmb = q_mask[qi*128 + r]*100.0f;
            float P[25];
            #pragma unroll
            for (int c=0;c<5;c++){
                float mx = sums[c*5];
                #pragma unroll
                for (int s=1;s<5;s++) mx = fmaxf(mx, sums[c*5+s]);
                float den = 0.f;
                #pragma unroll
                for (int s=0;s<5;s++){ P[c*5+s] = expf(sums[c*5+s]-mx); den += P[c*5+s]; }
                float inv = 1.0f/den;
                #pragma unroll
                for (int s=0;s<5;s++) P[c*5+s] *= inv;
            }
            if (lane < 25){
                int c = lane / 5, s = lane % 5;
                g_att[(size_t)(qi*5 + c)*640 + s*128 + r] = sums[lane] + qmb;
                g_P  [(size_t)(qi*5 + c)*640 + r*5 + s]   = P[lane];
            }
        }
        return;
    }
    if (blockIdx.x < 4*BNQ + 12){
        __shared__ float As[16][52];
        __shared__ float Bs[16][68];
        int tid = threadIdx.x;
        int tx = tid & 15, ty = tid >> 4;
        int n0 = (blockIdx.x - 4*BNQ) * 64;
        float acc[4][4];
        #pragma unroll
        for (int i=0;i<4;i++)
            #pragma unroll
            for (int j=0;j<4;j++) acc[i][j] = 0.f;
        int lm = tid >> 2, lk4 = (tid & 3)*4;
        for (int kt = 0; kt < 48; kt++){
            int kg = kt*16 + lk4;
            float4 a0 = (lm < 50) ? *(const float4*)(g_proto + (size_t)lm*DD + kg) : make_float4(0,0,0,0);
            float4 b0 = *(const float4*)(Bw + (size_t)(n0 + lm)*FD + kg);
            __syncthreads();
            if (lm < 50){
                As[lk4+0][lm]=a0.x; As[lk4+1][lm]=a0.y; As[lk4+2][lm]=a0.z; As[lk4+3][lm]=a0.w;
            }
            Bs[lk4+0][lm]=b0.x; Bs[lk4+1][lm]=b0.y; Bs[lk4+2][lm]=b0.z; Bs[lk4+3][lm]=b0.w;
            __syncthreads();
            if (ty < 13){
                #pragma unroll
                for (int kk=0;kk<16;kk++){
                    float a[4], b[4];
                    #pragma unroll
                    for (int i=0;i<4;i++) a[i] = (ty*4+i < 50) ? As[kk][ty*4+i] : 0.f;
                    float4 bv = *(const float4*)&Bs[kk][tx*4];
                    b[0]=bv.x; b[1]=bv.y; b[2]=bv.z; b[3]=bv.w;
                    #pragma unroll
                    for (int i=0;i<4;i++)
                        #pragma unroll
                        for (int j=0;j<4;j++) acc[i][j] += a[i]*b[j];
                }
            }
        }
        #pragma unroll
        for (int i=0;i<4;i++){
            int gm = ty*4 + i;
            if (gm < 50){
                #pragma unroll
                for (int j=0;j<4;j++)
                    g_pw2[(size_t)gm*DD + n0 + tx*4 + j] = acc[i][j];
            }
        }
        return;
    }
    int i = blockIdx.x - (4*BNQ + 12);
    dev_hgemm16<768,5120,false>(i % 6, i / 6, g_Q16, g_W16f, FD*2, g_T1, nullptr, ds);
}

// ================= light kernel: supp(200) + aprime(800) =================
__global__ void __launch_bounds__(256,4) k_light(const float* __restrict__ q_emb,
                                                 const float* __restrict__ q_mask)
{
    __shared__ float sbuf[4616];
    int b = blockIdx.x;
    int tid = threadIdx.x;
    if (b < 200){
        // supp -> fp16 FS hi + lo
        int bq = b;
        float* arow = sbuf;            // 640
        float* ps   = sbuf + 640;      // 3840
        float* sc   = sbuf + 4480;     // 8
        int qi = bq / 5;
        int pi = (bq / 100)*5 + (bq % 5);
        for (int i=tid;i<TAGS*128;i+=256) arow[i] = g_att[(size_t)bq*640 + i];
        for (int i=tid;i<TAGS*DD;i+=256) ps[i] = g_proto[(size_t)pi*TAGS*DD + i];
        __syncthreads();
        for (int s=0;s<TAGS;s++){
            float v = (tid<128) ? arow[s*128+tid] : -3.4e38f;
            float wm = warpMax(v);
            if ((tid&31)==0) sc[tid>>5] = wm;
            __syncthreads();
            float bm = sc[0];
            #pragma unroll
            for (int r=1;r<8;r++) bm = fmaxf(bm, sc[r]);
            float e = (tid<128) ? expf(v-bm) : 0.f;
            float wsm = warpSum(e);
            __syncthreads();
            if ((tid&31)==0) sc[tid>>5] = wsm;
            __syncthreads();
            float bs = sc[0];
            #pragma unroll
            for (int r=1;r<8;r++) bs += sc[r];
            if (tid<128) arow[s*128+tid] = e / bs;
            __syncthreads();
        }
        float acc[TAGS][3];
        #pragma unroll
        for (int s=0;s<TAGS;s++)
            #pragma unroll
            for (int j=0;j<3;j++) acc[s][j] = 0.f;
        const float* qb = q_emb + (size_t)qi*128*DD;
        #pragma unroll 4
        for (int q=0;q<128;q++){
            float w0=arow[q], w1=arow[128+q], w2=arow[256+q], w3=arow[384+q], w4=arow[512+q];
            #pragma unroll
            for (int j=0;j<3;j++){
                float e = qb[q*DD + tid + j*256];
                acc[0][j]+=w0*e; acc[1][j]+=w1*e; acc[2][j]+=w2*e; acc[3][j]+=w3*e; acc[4][j]+=w4*e;
            }
        }
        #pragma unroll
        for (int j=0;j<3;j++){
            int d = tid + j*256;
            #pragma unroll
            for (int s=0;s<TAGS;s++){
                float m1 = ps[s*DD+d];
                float m2 = acc[s][j];
                float f[4] = { m1, m2, fabsf(m1-m2), m1*m2 };
                size_t base = ((size_t)(bq*TAGS + s))*FD;
                #pragma unroll
                for (int cchunk=0;cchunk<4;cchunk++){
                    float v = f[cchunk];
                    __half hh = __float2half(v);
                    g_FS16 [base + cchunk*DD + d] = hh;
                    g_FS16l[base + cchunk*DD + d] = __float2half(v - __half2float(hh));
                }
            }
        }
        return;
    }
    // aprime: 800 blocks, (bq, q-quarter) — vectorized, fp16 out
    int i = b - 200;
    int bq = i % 200, q0 = (i / 200)*32;
    float* ps  = sbuf;            // 3840
    float* sP  = sbuf + 3840;     // 640
    float* sqm = sbuf + 4480;     // 128
    int qi = bq / 5;
    int pi = (bq / 100)*5 + (bq % 5);
    for (int j=tid;j<TAGS*DD;j+=256) ps[j] = g_proto[(size_t)pi*TAGS*DD + j];
    for (int j=tid;j<640;j+=256) sP[j] = g_P[(size_t)bq*640 + j];
    if (tid < 128) sqm[tid] = q_mask[qi*128 + tid];
    __syncthreads();
    const float4* ps4 = (const float4*)ps;
    for (int q = q0; q < q0 + 32; q++){
        float p0=sP[q*5+0], p1=sP[q*5+1], p2=sP[q*5+2], p3=sP[q*5+3], p4=sP[q*5+4];
        float qm = sqm[q];
        const float4* qr4 = (const float4*)(q_emb + ((size_t)qi*128 + q)*DD);
        size_t base = ((size_t)bq*128 + q)*1536;
        if (tid < 192){
            int d4 = tid;
            float4 qv = qr4[d4];
            float4 t0 = ps4[d4], t1v = ps4[192+d4], t2v = ps4[384+d4],
                   t3v = ps4[576+d4], t4v = ps4[768+d4];
            float m2x = qm*(p0*t0.x + p1*t1v.x + p2*t2v.x + p3*t3v.x + p4*t4v.x);
            float m2y = qm*(p0*t0.y + p1*t1v.y + p2*t2v.y + p3*t3v.y + p4*t4v.y);
            float m2z = qm*(p0*t0.z + p1*t1v.z + p2*t2v.z + p3*t3v.z + p4*t4v.z);
            float m2w = qm*(p0*t0.w + p1*t1v.w + p2*t2v.w + p3*t3v.w + p4*t4v.w);
            float ax = fabsf(qv.x - m2x), ay = fabsf(qv.y - m2y),
                  az = fabsf(qv.z - m2z), aw = fabsf(qv.w - m2w);
            float px = qv.x*m2x, py = qv.y*m2y, pz = qv.z*m2z, pw = qv.w*m2w;
            uint2 ah, ph;
            ah.x = pack2h(ax, ay); ah.y = pack2h(az, aw);
            ph.x = pack2h(px, py); ph.y = pack2h(pz, pw);
            int d = d4*4;
            *(uint2*)((char*)g_A16h + (base + d)*2)      = ah;
            *(uint2*)((char*)g_A16h + (base + DD + d)*2) = ph;
        }
    }
}

// fused big: big_mma(1200) | es hgemm16_2p(48)
__global__ void __launch_bounds__(256,2) k_big(const float* __restrict__ q_mask,
                                               const float* __restrict__ proj_b)
{
    extern __shared__ __align__(128) char ds[];
    int b = blockIdx.x;
    if (b < 1200){ dev_big(b % 6, b / 6, q_mask, proj_b, ds); return; }
    int i = b - 1200;
    dev_hgemm16_2p<3072,1000,true,false>(i % 6, i / 6, g_FS16, g_FS16l, g_W16f, FD*2,
                                         g_es, proj_b, nullptr, nullptr, ds);
}

// ---------------- cat assembly -> fp16 hi + lo; also init out ----------------
__global__ void cat_kernel(const float* __restrict__ q_mask,
                           const float* __restrict__ rel_b2,
                           float* __restrict__ outp)
{
    int bq = blockIdx.x, tid = threadIdx.x;
    int qi = bq / 5;
    if (bq == 0 && tid < BQC) outp[tid] = rel_b2[0];
    __shared__ float sc[8];
    __shared__ float qs_s;
    float v = (tid < 128) ? q_mask[qi*128 + tid] : 0.f;
    float ws = warpSum(v);
    if ((tid&31)==0) sc[tid>>5] = ws;
    __syncthreads();
    if (tid == 0){
        float q = 0.f;
        #pragma unroll
        for (int r=0;r<8;r++) q += sc[r];
        qs_s = q;
    }
    __syncthreads();
    float qs = qs_s;
    #pragma unroll
    for (int j=0;j<3;j++){
        int d = tid + j*256;
        float mx = 0.f, sm = 0.f;
        #pragma unroll
        for (int s=0;s<TAGS;s++){
            float e = g_es[((size_t)(bq*TAGS + s))*DD + d];
            mx = fmaxf(mx, e); sm += e;
        }
        float f[4] = { g_eqmax[(size_t)bq*DD + d],
                       g_eqsum[(size_t)bq*DD + d] / qs,
                       mx, sm * 0.2f };
        size_t b = (size_t)bq*FD;
        #pragma unroll
        for (int cchunk=0;cchunk<4;cchunk++){
            float val = f[cchunk];
            __half hh = __float2half(val);
            g_C16 [b + cchunk*DD + d] = hh;
            g_C16l[b + cchunk*DD + d] = __float2half(val - __half2float(hh));
        }
    }
}

// ---------------- h + logits fused: out += relu(cat@rel_w1^T + b1) . rel_w2 ----
__global__ void __launch_bounds__(256,2) k_h(const float* __restrict__ rel_b1,
                                             const float* __restrict__ rel_w2,
                                             float* __restrict__ outp)
{
    extern __shared__ __align__(128) char ds[];
    dev_hgemm16_2p<3072,200,true,true>(blockIdx.x, blockIdx.y, g_C16, g_C16l, g_RW16, FD*2,
                                       nullptr, rel_b1, rel_w2, outp, ds);
}

// ---------------- launcher ----------------
extern "C" void kernel_launch(void* const* d_in, const int* in_sizes, int n_in,
                              void* d_out, int out_size)
{
    const float* s_emb   = (const float*)d_in[0];
    const float* q_emb   = (const float*)d_in[1];
    const float* s_mask  = (const float*)d_in[2];
    const float* q_mask  = (const float*)d_in[3];
    const float* s_label = (const float*)d_in[4];
    const float* proj_w  = (const float*)d_in[5];
    const float* proj_b  = (const float*)d_in[6];
    const float* rel_w1  = (const float*)d_in[7];
    const float* rel_b1  = (const float*)d_in[8];
    const float* rel_w2  = (const float*)d_in[9];
    const float* rel_b2  = (const float*)d_in[10];
    float* out = (float*)d_out;

    static bool attr_set = false;
    if (!attr_set){
        cudaFuncSetAttribute(k_big, cudaFuncAttributeMaxDynamicSharedMemorySize, DSMEM2);
        cudaFuncSetAttribute(k_h,   cudaFuncAttributeMaxDynamicSharedMemorySize, DSMEM2);
        cudaFuncSetAttribute(k_att_pw2_t1, cudaFuncAttributeMaxDynamicSharedMemorySize, 25*DD*4);
        attr_set = true;
    }

    k_prep          <<<50 + 2*WBLK + QBLK, 256>>>(s_emb, s_mask, s_label, proj_w, rel_w1, q_emb);
    proto_avg_kernel<<<150, 256>>>();
    k_att_pw2_t1    <<<4*BNQ + 12 + 240, 256, 25*DD*4>>>(q_emb, q_mask, proj_w + DD);
    k_light         <<<1000, 256>>>(q_emb, q_mask);
    k_big           <<<1248, 256, DSMEM2>>>(q_mask, proj_b);
    cat_kernel      <<<BQC, 256>>>(q_mask, rel_b2, out);
    k_h             <<<dim3(6,2), 256, DSMEM2>>>(rel_b1, rel_w2, out);
}

// round 16
// speedup vs baseline: 1.0916x; 1.0916x over previous
#include <cuda_runtime.h>
#include <cuda_bf16.h>
#include <cuda_fp16.h>
#include <math.h>
#include <stdint.h>

// Problem constants (fixed by setup_inputs)
#define DD    768
#define TAGS  5
#define LQ    128
#define BQC   200      // B*N*Q*N
#define BNQ   40       // B*N*Q
#define BNKC  50       // B*N*K
#define NPROT 10       // B*N
#define FD    3072     // 4*D
#define MBIG  25600    // BQC*LQ

// ---------------- scratch (device globals) --------------
__device__ float g_protok[BNKC*TAGS*DD];
__device__ float g_proto [NPROT*TAGS*DD];
__device__ float g_pw2   [NPROT*TAGS*DD];
__device__ float g_att   [BQC*TAGS*LQ];
__device__ float g_P     [BQC*LQ*TAGS];
__device__ __half g_A16h[(size_t)MBIG*1536];     // fp16 big-GEMM A
__device__ __half g_W16f[(size_t)DD*FD];         // fp16 proj_w (full)
__device__ __half g_RW16[(size_t)DD*FD];         // fp16 rel_w1
__device__ __half g_Q16 [(size_t)BNQ*LQ*DD];     // fp16 q_emb
__device__ __half g_FS16[(size_t)1024*FD];       // fp16 fuse-support rows (hi)
__device__ __half g_FS16l[(size_t)1024*FD];      // fp16 lo residual
__device__ __half g_C16 [(size_t)256*FD];        // fp16 cat rows (hi)
__device__ __half g_C16l[(size_t)256*FD];        // fp16 lo residual
__device__ float g_T1    [BNQ*LQ*DD];
__device__ float g_es    [BQC*TAGS*DD];
__device__ float g_eqmax [BQC*DD];
__device__ float g_eqsum [BQC*DD];

__device__ __forceinline__ float warpMax(float v){
    #pragma unroll
    for (int o=16;o;o>>=1) v = fmaxf(v, __shfl_xor_sync(0xffffffffu, v, o));
    return v;
}
__device__ __forceinline__ float warpSum(float v){
    #pragma unroll
    for (int o=16;o;o>>=1) v += __shfl_xor_sync(0xffffffffu, v, o);
    return v;
}

// ================= HMMA helpers =================
__device__ __forceinline__ uint32_t smem_u32(const void* p) {
    uint32_t a;
    asm("{ .reg .u64 t; cvta.to.shared.u64 t, %1; cvt.u32.u64 %0, t; }" : "=r"(a) : "l"(p));
    return a;
}
__device__ __forceinline__ void cp16(uint32_t dst, const void* src){
    asm volatile("cp.async.cg.shared.global [%0], [%1], 16;" :: "r"(dst), "l"(src) : "memory");
}
__device__ __forceinline__ void cp_commit(){ asm volatile("cp.async.commit_group;" ::: "memory"); }
template<int N> __device__ __forceinline__ void cp_waitg(){
    asm volatile("cp.async.wait_group %0;" :: "n"(N) : "memory");
}
__device__ __forceinline__ void ldsm4(uint32_t a, uint32_t* r){
    asm volatile("ldmatrix.sync.aligned.m8n8.x4.shared.b16 {%0,%1,%2,%3}, [%4];"
        : "=r"(r[0]),"=r"(r[1]),"=r"(r[2]),"=r"(r[3]) : "r"(a));
}
__device__ __forceinline__ void mma16816h(float* c, const uint32_t* a, const uint32_t* b){
    asm volatile("mma.sync.aligned.m16n8k16.row.col.f32.f16.f16.f32 "
        "{%0,%1,%2,%3},{%4,%5,%6,%7},{%8,%9},{%0,%1,%2,%3};"
        : "+f"(c[0]),"+f"(c[1]),"+f"(c[2]),"+f"(c[3])
        : "r"(a[0]),"r"(a[1]),"r"(a[2]),"r"(a[3]), "r"(b[0]),"r"(b[1]));
}
__device__ __forceinline__ uint32_t tile_off(int m, int k8){
    return (uint32_t)((m*4 + (k8 ^ ((m>>1)&3))) << 4);
}
__device__ __forceinline__ uint32_t pack2h(float a, float b){
    return (uint32_t)__half_as_ushort(__float2half(a))
         | ((uint32_t)__half_as_ushort(__float2half(b)) << 16);
}

#define TBUF  8192
#define HSTG  (2*TBUF)       // fp16 1-product stage: A | B
#define HSTG2 (3*TBUF)       // fp16 2-product stage: Ah | Al | B
#define DSMEM2 (3*HSTG2)     // 72 KB

// ================= fp16 single-product HMMA GEMM =================
template<int KDIM, int MDIM, bool RELU>
__device__ void dev_hgemm16(int bx, int by,
                            const __half* __restrict__ A_,
                            const __half* __restrict__ B_, int bsb,
                            float* __restrict__ C,
                            const float* __restrict__ bias,
                            char* ds)
{
    constexpr int NC = KDIM / 32;
    int tid = threadIdx.x;
    int lane = tid & 31, wid = tid >> 5;
    int wm = wid & 1, wn = wid >> 1;
    int m0 = by * 128, n0 = bx * 128;
    uint32_t sbase = smem_u32(ds);

    const char* gA = (const char*)A_ + (size_t)m0*KDIM*2;
    const char* gB = (const char*)B_ + (size_t)n0*bsb;

    float acc[4][4][4];
    #pragma unroll
    for (int a=0;a<4;a++)
        #pragma unroll
        for (int b=0;b<4;b++)
            #pragma unroll
            for (int r=0;r<4;r++) acc[a][b][r] = 0.f;

    int r0 = tid >> 2, k80 = tid & 3;
    int r1 = r0 + 64;
    uint32_t d0 = tile_off(r0, k80);
    uint32_t d1 = tile_off(r1, k80);

    auto issue = [&](int c){
        size_t koff = (size_t)c*64 + (size_t)k80*16;
        uint32_t sb = sbase + (c % 3)*HSTG;
        size_t sa0 = (size_t)r0*(KDIM*2) + koff;
        size_t sa1 = (size_t)r1*(KDIM*2) + koff;
        size_t sb0 = (size_t)r0*bsb + koff;
        size_t sb1 = (size_t)r1*bsb + koff;
        cp16(sb + d0,        gA + sa0);  cp16(sb + d1,        gA + sa1);
        cp16(sb + TBUF + d0, gB + sb0);  cp16(sb + TBUF + d1, gB + sb1);
        cp_commit();
    };

    issue(0);
    issue(1);

    int a_m  = (lane & 15);
    int a_k8 = (lane >> 4);
    int b_n  = (lane & 7) + ((lane >> 4) << 3);
    int b_k8 = (lane >> 3) & 1;

    for (int c = 0; c < NC; c++){
        if (c + 1 < NC) cp_waitg<1>(); else cp_waitg<0>();
        __syncthreads();
        uint32_t ah = sbase + (c % 3)*HSTG;
        uint32_t bh = ah + TBUF;
        #pragma unroll
        for (int ks = 0; ks < 2; ks++){
            int ks8 = ks*2;
            uint32_t Bhf[2][4], Af[4][4];
            #pragma unroll
            for (int p=0; p<2; p++){
                int n = wn*32 + p*16 + b_n;
                ldsm4(bh + tile_off(n, ks8 + b_k8), Bhf[p]);
            }
            #pragma unroll
            for (int mt=0; mt<4; mt++){
                int m = wm*64 + mt*16 + a_m;
                ldsm4(ah + tile_off(m, ks8 + a_k8), Af[mt]);
            }
            #pragma unroll
            for (int mt=0; mt<4; mt++)
                #pragma unroll
                for (int nt=0; nt<4; nt++)
                    mma16816h(acc[mt][nt], Af[mt], &Bhf[nt>>1][(nt&1)*2]);
        }
        if (c + 2 < NC) issue(c+2);
    }

    int row = lane >> 2, colb = (lane & 3)*2;
    #pragma unroll
    for (int mt=0; mt<4; mt++){
        #pragma unroll
        for (int h2=0; h2<2; h2++){
            int gm = m0 + wm*64 + mt*16 + row + h2*8;
            if (gm < MDIM){
                #pragma unroll
                for (int nt=0; nt<4; nt++){
                    int cl = wn*32 + nt*8 + colb;
                    int gn = n0 + cl;
                    float v0 = acc[mt][nt][h2*2+0];
                    float v1 = acc[mt][nt][h2*2+1];
                    if (RELU){
                        v0 = fmaxf(v0 + bias[gn], 0.f);
                        v1 = fmaxf(v1 + bias[gn+1], 0.f);
                    }
                    C[(size_t)gm*DD + gn]   = v0;
                    C[(size_t)gm*DD + gn+1] = v1;
                }
            }
        }
    }
}

// ================= fp16 2-product HMMA GEMM (A = hi + lo) =================
template<int KDIM, int MDIM, bool RELU, bool FUSE_LOGITS>
__device__ void dev_hgemm16_2p(int bx, int by,
                               const __half* __restrict__ Ah_,
                               const __half* __restrict__ Al_,
                               const __half* __restrict__ B_, int bsb,
                               float* __restrict__ C,
                               const float* __restrict__ bias,
                               const float* __restrict__ w2,
                               float* __restrict__ outp,
                               char* ds)
{
    constexpr int NC = KDIM / 32;
    int tid = threadIdx.x;
    int lane = tid & 31, wid = tid >> 5;
    int wm = wid & 1, wn = wid >> 1;
    int m0 = by * 128, n0 = bx * 128;
    uint32_t sbase = smem_u32(ds);

    const char* gAh = (const char*)Ah_ + (size_t)m0*KDIM*2;
    const char* gAl = (const char*)Al_ + (size_t)m0*KDIM*2;
    const char* gB  = (const char*)B_ + (size_t)n0*bsb;

    float acc[4][4][4];
    #pragma unroll
    for (int a=0;a<4;a++)
        #pragma unroll
        for (int b=0;b<4;b++)
            #pragma unroll
            for (int r=0;r<4;r++) acc[a][b][r] = 0.f;

    int r0 = tid >> 2, k80 = tid & 3;
    int r1 = r0 + 64;
    uint32_t d0 = tile_off(r0, k80);
    uint32_t d1 = tile_off(r1, k80);

    auto issue = [&](int c){
        size_t koff = (size_t)c*64 + (size_t)k80*16;
        uint32_t sb = sbase + (c % 3)*HSTG2;
        size_t sa0 = (size_t)r0*(KDIM*2) + koff;
        size_t sa1 = (size_t)r1*(KDIM*2) + koff;
        size_t sb0 = (size_t)r0*bsb + koff;
        size_t sb1 = (size_t)r1*bsb + koff;
        cp16(sb + d0,          gAh + sa0);  cp16(sb + d1,          gAh + sa1);
        cp16(sb + TBUF + d0,   gAl + sa0);  cp16(sb + TBUF + d1,   gAl + sa1);
        cp16(sb + 2*TBUF + d0, gB + sb0);   cp16(sb + 2*TBUF + d1, gB + sb1);
        cp_commit();
    };

    issue(0);
    issue(1);

    int a_m  = (lane & 15);
    int a_k8 = (lane >> 4);
    int b_n  = (lane & 7) + ((lane >> 4) << 3);
    int b_k8 = (lane >> 3) & 1;

    for (int c = 0; c < NC; c++){
        if (c + 1 < NC) cp_waitg<1>(); else cp_waitg<0>();
        __syncthreads();
        uint32_t ah = sbase + (c % 3)*HSTG2;
        uint32_t al = ah + TBUF;
        uint32_t bh = ah + 2*TBUF;
        #pragma unroll
        for (int ks = 0; ks < 2; ks++){
            int ks8 = ks*2;
            uint32_t Bhf[2][4], Af[4][4];
            #pragma unroll
            for (int p=0; p<2; p++){
                int n = wn*32 + p*16 + b_n;
                ldsm4(bh + tile_off(n, ks8 + b_k8), Bhf[p]);
            }
            #pragma unroll
            for (int mt=0; mt<4; mt++){
                int m = wm*64 + mt*16 + a_m;
                ldsm4(ah + tile_off(m, ks8 + a_k8), Af[mt]);
            }
            #pragma unroll
            for (int mt=0; mt<4; mt++)
                #pragma unroll
                for (int nt=0; nt<4; nt++)
                    mma16816h(acc[mt][nt], Af[mt], &Bhf[nt>>1][(nt&1)*2]);
            #pragma unroll
            for (int mt=0; mt<4; mt++){
                int m = wm*64 + mt*16 + a_m;
                ldsm4(al + tile_off(m, ks8 + a_k8), Af[mt]);
            }
            #pragma unroll
            for (int mt=0; mt<4; mt++)
                #pragma unroll
                for (int nt=0; nt<4; nt++)
                    mma16816h(acc[mt][nt], Af[mt], &Bhf[nt>>1][(nt&1)*2]);
        }
        if (c + 2 < NC) issue(c+2);
    }

    int row = lane >> 2, colb = (lane & 3)*2;
    #pragma unroll
    for (int mt=0; mt<4; mt++){
        #pragma unroll
        for (int h2=0; h2<2; h2++){
            int gm = m0 + wm*64 + mt*16 + row + h2*8;
            if (gm < MDIM){
                float part = 0.f;
                #pragma unroll
                for (int nt=0; nt<4; nt++){
                    int cl = wn*32 + nt*8 + colb;
                    int gn = n0 + cl;
                    float v0 = acc[mt][nt][h2*2+0];
                    float v1 = acc[mt][nt][h2*2+1];
                    if (RELU){
                        v0 = fmaxf(v0 + bias[gn], 0.f);
                        v1 = fmaxf(v1 + bias[gn+1], 0.f);
                    }
                    if (FUSE_LOGITS){
                        part += v0*w2[gn] + v1*w2[gn+1];
                    } else {
                        C[(size_t)gm*DD + gn]   = v0;
                        C[(size_t)gm*DD + gn+1] = v1;
                    }
                }
                if (FUSE_LOGITS) atomicAdd(&outp[gm], part);
            }
        }
    }
}

// ================= big GEMM device core (fp16 1-product, fused epilogue) ========
#define NCCH  48
__device__ void dev_big(int bx, int by,
                        const float* __restrict__ q_mask,
                        const float* __restrict__ proj_b,
                        char* ds)
{
    __shared__ float s_pwr[5*128];
    __shared__ float s_P[640];
    __shared__ float s_qm[128];
    __shared__ float s_bias[128];
    __shared__ float s_rmax[2][128];
    __shared__ float s_rsum[2][128];

    int tid = threadIdx.x;
    int lane = tid & 31, wid = tid >> 5;
    int wm = wid & 1;
    int wn = wid >> 1;
    int bq  = by;
    int n0  = bx * 128;
    int qi  = bq / 5;
    int pi  = (bq / 100)*5 + (bq % 5);

    uint32_t sbase = smem_u32(ds);

    for (int i = tid; i < 5*128; i += 256){
        int s = i >> 7, c = i & 127;
        s_pwr[i] = g_pw2[((size_t)pi*5 + s)*DD + n0 + c];
    }
    for (int i = tid; i < 640; i += 256) s_P[i] = g_P[(size_t)bq*640 + i];
    if (tid < 128){ s_qm[tid] = q_mask[qi*128 + tid]; s_bias[tid] = proj_b[n0 + tid]; }

    const char* gAh = (const char*)g_A16h + (size_t)bq*128*3072;
    const char* gBh = (const char*)g_W16f + (size_t)n0*6144 + 3072;

    float acc[4][4][4];
    #pragma unroll
    for (int a=0;a<4;a++)
        #pragma unroll
        for (int b=0;b<4;b++)
            #pragma unroll
            for (int r=0;r<4;r++) acc[a][b][r] = 0.f;

    int r0 = tid >> 2, k80 = tid & 3;
    int r1 = r0 + 64;
    uint32_t d0 = tile_off(r0, k80);
    uint32_t d1 = tile_off(r1, k80);

    auto issue = [&](int c){
        size_t koff = (size_t)c*64 + (size_t)k80*16;
        uint32_t sb = sbase + (c % 3)*HSTG;
        size_t sa0 = (size_t)r0*3072 + koff;
        size_t sa1 = (size_t)r1*3072 + koff;
        size_t sb0 = (size_t)r0*6144 + koff;
        size_t sb1 = (size_t)r1*6144 + koff;
        cp16(sb + d0,        gAh + sa0);  cp16(sb + d1,        gAh + sa1);
        cp16(sb + TBUF + d0, gBh + sb0);  cp16(sb + TBUF + d1, gBh + sb1);
        cp_commit();
    };

    issue(0);
    issue(1);

    int a_m  = (lane & 15);
    int a_k8 = (lane >> 4);
    int b_n  = (lane & 7) + ((lane >> 4) << 3);
    int b_k8 = (lane >> 3) & 1;

    for (int c = 0; c < NCCH; c++){
        if (c + 1 < NCCH) cp_waitg<1>(); else cp_waitg<0>();
        __syncthreads();
        uint32_t ah = sbase + (c % 3)*HSTG;
        uint32_t bh = ah + TBUF;
        #pragma unroll
        for (int ks = 0; ks < 2; ks++){
            int ks8 = ks*2;
            uint32_t Bhf[2][4], Af[4][4];
            #pragma unroll
            for (int p=0; p<2; p++){
                int n = wn*32 + p*16 + b_n;
                ldsm4(bh + tile_off(n, ks8 + b_k8), Bhf[p]);
            }
            #pragma unroll
            for (int mt=0; mt<4; mt++){
                int m = wm*64 + mt*16 + a_m;
                ldsm4(ah + tile_off(m, ks8 + a_k8), Af[mt]);
            }
            #pragma unroll
            for (int mt=0; mt<4; mt++)
                #pragma unroll
                for (int nt=0; nt<4; nt++)
                    mma16816h(acc[mt][nt], Af[mt], &Bhf[nt>>1][(nt&1)*2]);
        }
        if (c + 2 < NCCH) issue(c+2);
    }

    // fused epilogue
    int row = lane >> 2, colb = (lane & 3)*2;
    float lmax[4][2], lsum[4][2];
    #pragma unroll
    for (int nt=0; nt<4; nt++)
        #pragma unroll
        for (int j=0;j<2;j++){ lmax[nt][j] = 0.f; lsum[nt][j] = 0.f; }

    #pragma unroll
    for (int mt=0; mt<4; mt++){
        #pragma unroll
        for (int h2=0; h2<2; h2++){
            int q = wm*64 + mt*16 + row + h2*8;
            float qm = s_qm[q];
            float p0=s_P[q*5+0], p1=s_P[q*5+1], p2=s_P[q*5+2], p3=s_P[q*5+3], p4=s_P[q*5+4];
            const float* t1row = g_T1 + ((size_t)qi*128 + q)*DD + n0;
            #pragma unroll
            for (int nt=0; nt<4; nt++){
                int cl = wn*32 + nt*8 + colb;
                float2 t1 = *(const float2*)(t1row + cl);
                float t2a = qm*(p0*s_pwr[cl] + p1*s_pwr[128+cl] + p2*s_pwr[256+cl]
                              + p3*s_pwr[384+cl] + p4*s_pwr[512+cl]);
                float t2b = qm*(p0*s_pwr[cl+1] + p1*s_pwr[128+cl+1] + p2*s_pwr[256+cl+1]
                              + p3*s_pwr[384+cl+1] + p4*s_pwr[512+cl+1]);
                float v0 = fmaxf(acc[mt][nt][h2*2+0] + t1.x + t2a + s_bias[cl], 0.f);
                float v1 = fmaxf(acc[mt][nt][h2*2+1] + t1.y + t2b + s_bias[cl+1], 0.f);
                lmax[nt][0] = fmaxf(lmax[nt][0], v0); lsum[nt][0] += v0;
                lmax[nt][1] = fmaxf(lmax[nt][1], v1); lsum[nt][1] += v1;
            }
        }
    }
    #pragma unroll
    for (int o = 4; o <= 16; o <<= 1){
        #pragma unroll
        for (int nt=0; nt<4; nt++)
            #pragma unroll
            for (int j=0;j<2;j++){
                lmax[nt][j] = fmaxf(lmax[nt][j], __shfl_xor_sync(0xffffffffu, lmax[nt][j], o));
                lsum[nt][j] += __shfl_xor_sync(0xffffffffu, lsum[nt][j], o);
            }
    }
    if (row == 0){
        #pragma unroll
        for (int nt=0; nt<4; nt++){
            int cl = wn*32 + nt*8 + colb;
            s_rmax[wm][cl]   = lmax[nt][0];  s_rsum[wm][cl]   = lsum[nt][0];
            s_rmax[wm][cl+1] = lmax[nt][1];  s_rsum[wm][cl+1] = lsum[nt][1];
        }
    }
    __syncthreads();
    if (tid < 128){
        g_eqmax[(size_t)bq*DD + n0 + tid] = fmaxf(s_rmax[0][tid], s_rmax[1][tid]);
        g_eqsum[(size_t)bq*DD + n0 + tid] = s_rsum[0][tid] + s_rsum[1][tid];
    }
}

// ================= prep paths =================
__device__ void dev_proto(int bnk, const float* __restrict__ s_emb,
                          const float* __restrict__ s_mask,
                          const float* __restrict__ s_label)
{
    __shared__ int   tags[128];
    __shared__ float wts[128];
    __shared__ float cnt[TAGS];
    int tid = threadIdx.x;
    if (tid < 128) {
        const float* lr = s_label + ((size_t)bnk*128 + tid)*TAGS;
        float best = lr[0]; int bi = 0;
        #pragma unroll
        for (int s=1;s<TAGS;s++){ float v = lr[s]; if (v > best){ best = v; bi = s; } }
        tags[tid] = bi;
        wts[tid]  = (bi == 0) ? s_mask[bnk*128 + tid] : 1.0f;
    }
    __syncthreads();
    if (tid < TAGS) {
        float c = 0.f;
        for (int t=0;t<128;t++) if (tags[t] == tid) c += wts[t];
        cnt[tid] = c;
    }
    __syncthreads();
    float acc[TAGS][3];
    #pragma unroll
    for (int k=0;k<TAGS;k++)
        #pragma unroll
        for (int j=0;j<3;j++) acc[k][j] = 0.f;
    const float* eb = s_emb + (size_t)bnk*128*DD;
    for (int t=0;t<128;t++){
        int tg = tags[t]; float w = wts[t];
        #pragma unroll
        for (int j=0;j<3;j++){
            float e = eb[t*DD + tid + j*256];
            #pragma unroll
            for (int k=0;k<TAGS;k++)
                acc[k][j] += ((tg == k) ? w : 0.0f) * e;
        }
    }
    #pragma unroll
    for (int k=0;k<TAGS;k++){
        float c = cnt[k];
        float inv = (c > 0.f) ? (1.0f / fmaxf(c, 1.0f)) : 0.0f;
        #pragma unroll
        for (int j=0;j<3;j++){
            int d = tid + j*256;
            g_protok[((size_t)bnk*TAGS + k)*DD + d] = (c > 0.f) ? acc[k][j]*inv : 0.0f;
        }
    }
}

__device__ __forceinline__ void cast8(const float* __restrict__ src,
                                      __half* __restrict__ dst, size_t i0)
{
    float4 a = *(const float4*)(src + i0);
    float4 b = *(const float4*)(src + i0 + 4);
    uint4 o;
    o.x = pack2h(a.x, a.y); o.y = pack2h(a.z, a.w);
    o.z = pack2h(b.x, b.y); o.w = pack2h(b.z, b.w);
    *(uint4*)(dst + i0) = o;
}

#define WBLK 1152   // DD*FD/2048
#define QBLK 1920   // BNQ*LQ*DD/2048

__global__ void __launch_bounds__(256) k_prep(const float* __restrict__ s_emb,
                                              const float* __restrict__ s_mask,
                                              const float* __restrict__ s_label,
                                              const float* __restrict__ proj_w,
                                              const float* __restrict__ rel_w1,
                                              const float* __restrict__ q_emb)
{
    int b = blockIdx.x;
    if (b < 50){ dev_proto(b, s_emb, s_mask, s_label); return; }
    int tid = threadIdx.x;
    if (b < 50 + WBLK){ cast8(proj_w, g_W16f, ((size_t)(b-50)*256 + tid)*8); return; }
    if (b < 50 + 2*WBLK){ cast8(rel_w1, g_RW16, ((size_t)(b-50-WBLK)*256 + tid)*8); return; }
    cast8(q_emb, g_Q16, ((size_t)(b-50-2*WBLK)*256 + tid)*8);
}

__global__ void proto_avg_kernel()
{
    int i = blockIdx.x*256 + threadIdx.x;
    int pi = i / (TAGS*DD), rem = i % (TAGS*DD);
    float s = 0.f;
    #pragma unroll
    for (int k=0;k<5;k++) s += g_protok[((size_t)(pi*5 + k))*(TAGS*DD) + rem];
    g_proto[i] = s * 0.2f;
}

// ================= att (2-way split, fused s-softmax) | pw2 | T1 hgemm16 =========
__global__ void __launch_bounds__(256,2) k_att_pw2_t1(const float* __restrict__ q_emb,
                                                      const float* __restrict__ q_mask,
                                                      const float* __restrict__ Bw)
{
    extern __shared__ __align__(128) char ds[];
    if (blockIdx.x < 2*BNQ){
        float* sp = (float*)ds;            // 25 x 768
        int qi = blockIdx.x >> 1, half = blockIdx.x & 1;
        int tid = threadIdx.x;
        int b = qi / 20;
        const float* pb = g_proto + (size_t)b*25*DD;
        for (int i = tid; i < 25*DD; i += 256) sp[i] = pb[i];
        __syncthreads();
        int wid = tid >> 5, lane = tid & 31;
        const float4* sp4 = (const float4*)sp;
        for (int r = half*64 + wid; r < half*64 + 64; r += 8){
            const float4* qr4 = (const float4*)(q_emb + ((size_t)qi*128 + r)*DD);
            float acc[25];
            #pragma unroll
            for (int t=0;t<25;t++) acc[t] = 0.f;
            for (int d4 = lane; d4 < 192; d4 += 32){
                float4 qv = qr4[d4];
                #pragma unroll
                for (int t=0;t<25;t++){
                    float4 sv = sp4[t*192 + d4];
                    acc[t] += qv.x*sv.x + qv.y*sv.y + qv.z*sv.z + qv.w*sv.w;
                }
            }
            float sums[25];
            #pragma unroll
            for (int t=0;t<25;t++) sums[t] = warpSum(acc[t]);
            float qmb = q_mask[qi*128 + r]*100.0f;
            float P[25];
            #pragma unroll
            for (int c=0;c<5;c++){
                float mx = sums[c*5];
                #pragma unroll
                for (int s=1;s<5;s++) mx = fmaxf(mx, sums[c*5+s]);
                float den = 0.f;
                #pragma unroll
                for (int s=0;s<5;s++){ P[c*5+s] = expf(sums[c*5+s]-mx); den += P[c*5+s]; }
                float inv = 1.0f/den;
                #pragma unroll
                for (int s=0;s<5;s++) P[c*5+s] *= inv;
            }
            if (lane < 25){
                int c = lane / 5, s = lane % 5;
                g_att[(size_t)(qi*5 + c)*640 + s*128 + r] = sums[lane] + qmb;
                g_P  [(size_t)(qi*5 + c)*640 + r*5 + s]   = P[lane];
            }
        }
        return;
    }
    if (blockIdx.x < 2*BNQ + 12){
        __shared__ float As[16][52];
        __shared__ float Bs[16][68];
        int tid = threadIdx.x;
        int tx = tid & 15, ty = tid >> 4;
        int n0 = (blockIdx.x - 2*BNQ) * 64;
        float acc[4][4];
        #pragma unroll
        for (int i=0;i<4;i++)
            #pragma unroll
            for (int j=0;j<4;j++) acc[i][j] = 0.f;
        int lm = tid >> 2, lk4 = (tid & 3)*4;
        for (int kt = 0; kt < 48; kt++){
            int kg = kt*16 + lk4;
            float4 a0 = (lm < 50) ? *(const float4*)(g_proto + (size_t)lm*DD + kg) : make_float4(0,0,0,0);
            float4 b0 = *(const float4*)(Bw + (size_t)(n0 + lm)*FD + kg);
            __syncthreads();
            if (lm < 50){
                As[lk4+0][lm]=a0.x; As[lk4+1][lm]=a0.y; As[lk4+2][lm]=a0.z; As[lk4+3][lm]=a0.w;
            }
            Bs[lk4+0][lm]=b0.x; Bs[lk4+1][lm]=b0.y; Bs[lk4+2][lm]=b0.z; Bs[lk4+3][lm]=b0.w;
            __syncthreads();
            if (ty < 13){
                #pragma unroll
                for (int kk=0;kk<16;kk++){
                    float a[4], b[4];
                    #pragma unroll
                    for (int i=0;i<4;i++) a[i] = (ty*4+i < 50) ? As[kk][ty*4+i] : 0.f;
                    float4 bv = *(const float4*)&Bs[kk][tx*4];
                    b[0]=bv.x; b[1]=bv.y; b[2]=bv.z; b[3]=bv.w;
                    #pragma unroll
                    for (int i=0;i<4;i++)
                        #pragma unroll
                        for (int j=0;j<4;j++) acc[i][j] += a[i]*b[j];
                }
            }
        }
        #pragma unroll
        for (int i=0;i<4;i++){
            int gm = ty*4 + i;
            if (gm < 50){
                #pragma unroll
                for (int j=0;j<4;j++)
                    g_pw2[(size_t)gm*DD + n0 + tx*4 + j] = acc[i][j];
            }
        }
        return;
    }
    int i = blockIdx.x - (2*BNQ + 12);
    dev_hgemm16<768,5120,false>(i % 6, i / 6, g_Q16, g_W16f, FD*2, g_T1, nullptr, ds);
}

// ================= light kernel: supp(200) + aprime(800) =================
__global__ void __launch_bounds__(256,4) k_light(const float* __restrict__ q_emb,
                                                 const float* __restrict__ q_mask)
{
    __shared__ float sbuf[4616];
    int b = blockIdx.x;
    int tid = threadIdx.x;
    if (b < 200){
        // supp -> fp16 FS hi + lo
        int bq = b;
        float* arow = sbuf;            // 640
        float* ps   = sbuf + 640;      // 3840
        float* sc   = sbuf + 4480;     // 8
        int qi = bq / 5;
        int pi = (bq / 100)*5 + (bq % 5);
        for (int i=tid;i<TAGS*128;i+=256) arow[i] = g_att[(size_t)bq*640 + i];
        for (int i=tid;i<TAGS*DD;i+=256) ps[i] = g_proto[(size_t)pi*TAGS*DD + i];
        __syncthreads();
        for (int s=0;s<TAGS;s++){
            float v = (tid<128) ? arow[s*128+tid] : -3.4e38f;
            float wm = warpMax(v);
            if ((tid&31)==0) sc[tid>>5] = wm;
            __syncthreads();
            float bm = sc[0];
            #pragma unroll
            for (int r=1;r<8;r++) bm = fmaxf(bm, sc[r]);
            float e = (tid<128) ? expf(v-bm) : 0.f;
            float wsm = warpSum(e);
            __syncthreads();
            if ((tid&31)==0) sc[tid>>5] = wsm;
            __syncthreads();
            float bs = sc[0];
            #pragma unroll
            for (int r=1;r<8;r++) bs += sc[r];
            if (tid<128) arow[s*128+tid] = e / bs;
            __syncthreads();
        }
        float acc[TAGS][3];
        #pragma unroll
        for (int s=0;s<TAGS;s++)
            #pragma unroll
            for (int j=0;j<3;j++) acc[s][j] = 0.f;
        const float* qb = q_emb + (size_t)qi*128*DD;
        #pragma unroll 4
        for (int q=0;q<128;q++){
            float w0=arow[q], w1=arow[128+q], w2=arow[256+q], w3=arow[384+q], w4=arow[512+q];
            #pragma unroll
            for (int j=0;j<3;j++){
                float e = qb[q*DD + tid + j*256];
                acc[0][j]+=w0*e; acc[1][j]+=w1*e; acc[2][j]+=w2*e; acc[3][j]+=w3*e; acc[4][j]+=w4*e;
            }
        }
        #pragma unroll
        for (int j=0;j<3;j++){
            int d = tid + j*256;
            #pragma unroll
            for (int s=0;s<TAGS;s++){
                float m1 = ps[s*DD+d];
                float m2 = acc[s][j];
                float f[4] = { m1, m2, fabsf(m1-m2), m1*m2 };
                size_t base = ((size_t)(bq*TAGS + s))*FD;
                #pragma unroll
                for (int cchunk=0;cchunk<4;cchunk++){
                    float v = f[cchunk];
                    __half hh = __float2half(v);
                    g_FS16 [base + cchunk*DD + d] = hh;
                    g_FS16l[base + cchunk*DD + d] = __float2half(v - __half2float(hh));
                }
            }
        }
        return;
    }
    // aprime: 800 blocks, (bq, q-quarter) — vectorized, fp16 out
    int i = b - 200;
    int bq = i % 200, q0 = (i / 200)*32;
    float* ps  = sbuf;            // 3840
    float* sP  = sbuf + 3840;     // 640
    float* sqm = sbuf + 4480;     // 128
    int qi = bq / 5;
    int pi = (bq / 100)*5 + (bq % 5);
    for (int j=tid;j<TAGS*DD;j+=256) ps[j] = g_proto[(size_t)pi*TAGS*DD + j];
    for (int j=tid;j<640;j+=256) sP[j] = g_P[(size_t)bq*640 + j];
    if (tid < 128) sqm[tid] = q_mask[qi*128 + tid];
    __syncthreads();
    const float4* ps4 = (const float4*)ps;
    for (int q = q0; q < q0 + 32; q++){
        float p0=sP[q*5+0], p1=sP[q*5+1], p2=sP[q*5+2], p3=sP[q*5+3], p4=sP[q*5+4];
        float qm = sqm[q];
        const float4* qr4 = (const float4*)(q_emb + ((size_t)qi*128 + q)*DD);
        size_t base = ((size_t)bq*128 + q)*1536;
        if (tid < 192){
            int d4 = tid;
            float4 qv = qr4[d4];
            float4 t0 = ps4[d4], t1v = ps4[192+d4], t2v = ps4[384+d4],
                   t3v = ps4[576+d4], t4v = ps4[768+d4];
            float m2x = qm*(p0*t0.x + p1*t1v.x + p2*t2v.x + p3*t3v.x + p4*t4v.x);
            float m2y = qm*(p0*t0.y + p1*t1v.y + p2*t2v.y + p3*t3v.y + p4*t4v.y);
            float m2z = qm*(p0*t0.z + p1*t1v.z + p2*t2v.z + p3*t3v.z + p4*t4v.z);
            float m2w = qm*(p0*t0.w + p1*t1v.w + p2*t2v.w + p3*t3v.w + p4*t4v.w);
            float ax = fabsf(qv.x - m2x), ay = fabsf(qv.y - m2y),
                  az = fabsf(qv.z - m2z), aw = fabsf(qv.w - m2w);
            float px = qv.x*m2x, py = qv.y*m2y, pz = qv.z*m2z, pw = qv.w*m2w;
            uint2 ah, ph;
            ah.x = pack2h(ax, ay); ah.y = pack2h(az, aw);
            ph.x = pack2h(px, py); ph.y = pack2h(pz, pw);
            int d = d4*4;
            *(uint2*)((char*)g_A16h + (base + d)*2)      = ah;
            *(uint2*)((char*)g_A16h + (base + DD + d)*2) = ph;
        }
    }
}

// fused big: big_mma(1200) | es hgemm16_2p(48)
__global__ void __launch_bounds__(256,2) k_big(const float* __restrict__ q_mask,
                                               const float* __restrict__ proj_b)
{
    extern __shared__ __align__(128) char ds[];
    int b = blockIdx.x;
    if (b < 1200){ dev_big(b % 6, b / 6, q_mask, proj_b, ds); return; }
    int i = b - 1200;
    dev_hgemm16_2p<3072,1000,true,false>(i % 6, i / 6, g_FS16, g_FS16l, g_W16f, FD*2,
                                         g_es, proj_b, nullptr, nullptr, ds);
}

// ---------------- cat assembly -> fp16 hi + lo; also init out ----------------
__global__ void cat_kernel(const float* __restrict__ q_mask,
                           const float* __restrict__ rel_b2,
                           float* __restrict__ outp)
{
    int bq = blockIdx.x, tid = threadIdx.x;
    int qi = bq / 5;
    if (bq == 0 && tid < BQC) outp[tid] = rel_b2[0];
    __shared__ float sc[8];
    __shared__ float qs_s;
    float v = (tid < 128) ? q_mask[qi*128 + tid] : 0.f;
    float ws = warpSum(v);
    if ((tid&31)==0) sc[tid>>5] = ws;
    __syncthreads();
    if (tid == 0){
        float q = 0.f;
        #pragma unroll
        for (int r=0;r<8;r++) q += sc[r];
        qs_s = q;
    }
    __syncthreads();
    float qs = qs_s;
    #pragma unroll
    for (int j=0;j<3;j++){
        int d = tid + j*256;
        float mx = 0.f, sm = 0.f;
        #pragma unroll
        for (int s=0;s<TAGS;s++){
            float e = g_es[((size_t)(bq*TAGS + s))*DD + d];
            mx = fmaxf(mx, e); sm += e;
        }
        float f[4] = { g_eqmax[(size_t)bq*DD + d],
                       g_eqsum[(size_t)bq*DD + d] / qs,
                       mx, sm * 0.2f };
        size_t b = (size_t)bq*FD;
        #pragma unroll
        for (int cchunk=0;cchunk<4;cchunk++){
            float val = f[cchunk];
            __half hh = __float2half(val);
            g_C16 [b + cchunk*DD + d] = hh;
            g_C16l[b + cchunk*DD + d] = __float2half(val - __half2float(hh));
        }
    }
}

// ---------------- h + logits fused: out += relu(cat@rel_w1^T + b1) . rel_w2 ----
__global__ void __launch_bounds__(256,2) k_h(const float* __restrict__ rel_b1,
                                             const float* __restrict__ rel_w2,
                                             float* __restrict__ outp)
{
    extern __shared__ __align__(128) char ds[];
    dev_hgemm16_2p<3072,200,true,true>(blockIdx.x, blockIdx.y, g_C16, g_C16l, g_RW16, FD*2,
                                       nullptr, rel_b1, rel_w2, outp, ds);
}

// ---------------- launcher ----------------
extern "C" void kernel_launch(void* const* d_in, const int* in_sizes, int n_in,
                              void* d_out, int out_size)
{
    const float* s_emb   = (const float*)d_in[0];
    const float* q_emb   = (const float*)d_in[1];
    const float* s_mask  = (const float*)d_in[2];
    const float* q_mask  = (const float*)d_in[3];
    const float* s_label = (const float*)d_in[4];
    const float* proj_w  = (const float*)d_in[5];
    const float* proj_b  = (const float*)d_in[6];
    const float* rel_w1  = (const float*)d_in[7];
    const float* rel_b1  = (const float*)d_in[8];
    const float* rel_w2  = (const float*)d_in[9];
    const float* rel_b2  = (const float*)d_in[10];
    float* out = (float*)d_out;

    static bool attr_set = false;
    if (!attr_set){
        cudaFuncSetAttribute(k_big, cudaFuncAttributeMaxDynamicSharedMemorySize, DSMEM2);
        cudaFuncSetAttribute(k_h,   cudaFuncAttributeMaxDynamicSharedMemorySize, DSMEM2);
        cudaFuncSetAttribute(k_att_pw2_t1, cudaFuncAttributeMaxDynamicSharedMemorySize, 25*DD*4);
        attr_set = true;
    }

    k_prep          <<<50 + 2*WBLK + QBLK, 256>>>(s_emb, s_mask, s_label, proj_w, rel_w1, q_emb);
    proto_avg_kernel<<<150, 256>>>();
    k_att_pw2_t1    <<<2*BNQ + 12 + 240, 256, 25*DD*4>>>(q_emb, q_mask, proj_w + DD);
    k_light         <<<1000, 256>>>(q_emb, q_mask);
    k_big           <<<1248, 256, DSMEM2>>>(q_mask, proj_b);
    cat_kernel      <<<BQC, 256>>>(q_mask, rel_b2, out);
    k_h             <<<dim3(6,2), 256, DSMEM2>>>(rel_b1, rel_w2, out);
}